// round 5
// baseline (speedup 1.0000x reference)
#include <cuda_runtime.h>
#include <math.h>

#define TPB 256

// ---------------- shared-memory layout (floats) ----------------
// wfp   [1200]    reflect-padded waveform          @ 0
// cp    [1200]    reflect-padded cumsum            @ 1200
// dsp   [1200]    reflect-padded smoothed deriv    @ 2400
// buf   [1000]    d1 scratch, later o / y / p      @ 3600
// fnp   [3][1024] normalized features + halos      @ 4600
// f2p   [15][1104] f2 with 50/54 zero halos        @ 7672
// cwp   [15][104] W-weighted comb weights          @ 24232
// wsubp [15][3][24]                                @ 25792
// wcaP  [124]                                      @ 26872
// wxP   [124]                                      @ 26996
// wdvP  [124]                                      @ 27120
// wrlP  [104]                                      @ 27244
// red   [32]                                       @ 27348
// scal  [12]                                       @ 27380
// total 27392 floats = 109568 bytes
#define SMEM_FLOATS 27392

__device__ __forceinline__ float warpRMax(float v){
#pragma unroll
  for(int o=16;o>0;o>>=1) v=fmaxf(v,__shfl_xor_sync(0xffffffffu,v,o));
  return v;
}
__device__ __forceinline__ float warpRSum(float v){
#pragma unroll
  for(int o=16;o>0;o>>=1) v+=__shfl_xor_sync(0xffffffffu,v,o);
  return v;
}

__device__ __forceinline__ void bredMax(float v, float* red, float* out){
  int lane=threadIdx.x&31, wid=threadIdx.x>>5;
  v=warpRMax(v);
  if(lane==0) red[wid]=v;
  __syncthreads();
  if(threadIdx.x==0){
    float m=red[0];
#pragma unroll
    for(int i=1;i<TPB/32;i++) m=fmaxf(m,red[i]);
    *out=m;
  }
  __syncthreads();
}
__device__ __forceinline__ void bredSum(float v, float* red, float* out){
  int lane=threadIdx.x&31, wid=threadIdx.x>>5;
  v=warpRSum(v);
  if(lane==0) red[wid]=v;
  __syncthreads();
  if(threadIdx.x==0){
    float s=red[0];
#pragma unroll
    for(int i=1;i<TPB/32;i++) s+=red[i];
    *out=s;
  }
  __syncthreads();
}

// 4 consecutive outputs, sliding float4 window; out[j] += sum_k w[k]*src[j+k]
#define CONV4_BODY(x0,x1,wv,acc)                                               \
  acc[0]=fmaf(wv.x,x0.x,acc[0]); acc[1]=fmaf(wv.x,x0.y,acc[1]);                \
  acc[2]=fmaf(wv.x,x0.z,acc[2]); acc[3]=fmaf(wv.x,x0.w,acc[3]);                \
  acc[0]=fmaf(wv.y,x0.y,acc[0]); acc[1]=fmaf(wv.y,x0.z,acc[1]);                \
  acc[2]=fmaf(wv.y,x0.w,acc[2]); acc[3]=fmaf(wv.y,x1.x,acc[3]);                \
  acc[0]=fmaf(wv.z,x0.z,acc[0]); acc[1]=fmaf(wv.z,x0.w,acc[1]);                \
  acc[2]=fmaf(wv.z,x1.x,acc[2]); acc[3]=fmaf(wv.z,x1.y,acc[3]);                \
  acc[0]=fmaf(wv.w,x0.w,acc[0]); acc[1]=fmaf(wv.w,x1.x,acc[1]);                \
  acc[2]=fmaf(wv.w,x1.y,acc[2]); acc[3]=fmaf(wv.w,x1.z,acc[3]);

template<int NG>
__device__ __forceinline__ void conv4(const float* __restrict__ src,
                                      const float* __restrict__ w,
                                      float* __restrict__ acc){
  float4 x0 = *reinterpret_cast<const float4*>(src);
#pragma unroll
  for(int g=0; g<NG; g++){
    float4 x1 = *reinterpret_cast<const float4*>(src + 4*g + 4);
    float4 wv = *reinterpret_cast<const float4*>(w + 4*g);
    CONV4_BODY(x0,x1,wv,acc)
    x0=x1;
  }
}

__device__ __forceinline__ void conv4r(const float* __restrict__ src,
                                       const float* __restrict__ w,
                                       int ng, float* __restrict__ acc){
  float4 x0 = *reinterpret_cast<const float4*>(src);
#pragma unroll 2
  for(int g=0; g<ng; g++){
    float4 x1 = *reinterpret_cast<const float4*>(src + 4*g + 4);
    float4 wv = *reinterpret_cast<const float4*>(w + 4*g);
    CONV4_BODY(x0,x1,wv,acc)
    x0=x1;
  }
}

__global__ void __launch_bounds__(TPB,2) Spot_48610439856277_kernel(
  const float* __restrict__ g_wf, const float* __restrict__ g_mask,
  const float* __restrict__ g_spe,
  const float* __restrict__ g_wca, const float* __restrict__ g_wx,
  const float* __restrict__ g_wdv, const float* __restrict__ g_wrl,
  const float* __restrict__ g_wsub, const float* __restrict__ g_wcomb,
  const float* __restrict__ g_wp,
  float* __restrict__ g_out)
{
  extern __shared__ float sm[];
  float* wfp  = sm;
  float* cp   = sm + 1200;
  float* dsp  = sm + 2400;
  float* buf  = sm + 3600;
  float* fnp  = sm + 4600;
  float* f2p  = sm + 7672;
  float* cwp  = sm + 24232;
  float* wsubp= sm + 25792;
  float* wcaP = sm + 26872;
  float* wxP  = sm + 26996;
  float* wdvP = sm + 27120;
  float* wrlP = sm + 27244;
  float* red  = sm + 27348;
  float* scal = sm + 27380;

  const int tid = threadIdx.x;
  const int b   = blockIdx.x;
  const float* wf = g_wf  + (size_t)b*1000;
  const float* mk = g_mask+ (size_t)b*1000;
  float* outp     = g_out + (size_t)b*1000;

  // ---- loads: reflect-padded wf + weights (+ zero pads) ----
  for(int i=tid;i<1200;i+=TPB){
    int j=i-100; j = (j<0) ? -j : (j>999 ? 1998-j : j);
    wfp[i]=wf[j];
  }
  for(int i=tid;i<124;i+=TPB){
    float a = (i<121)? g_wca[i] : 0.f;
    float x = (i<121)? g_wx[i]  : 0.f;
    float d = (i<121)? g_wdv[i] : 0.f;
    wcaP[i]=a; wxP[i]=x; wdvP[i]=d;
  }
  for(int i=tid;i<104;i+=TPB) wrlP[i] = (i<101)? g_wrl[i] : 0.f;
  for(int i=tid;i<1080;i+=TPB){
    int m=i/72, rem=i%72, cin=rem/24, k=rem%24;
    wsubp[i] = (k<21)? g_wsub[(m*3+cin)*21+k] : 0.f;
  }
  for(int i=tid;i<15*50;i+=TPB){ int c=i/50,o=i%50; f2p[c*1104+o]=0.f; }
  for(int i=tid;i<15*54;i+=TPB){ int c=i/54,o=i%54; f2p[c*1104+1050+o]=0.f; }
  for(int i=tid;i<12;i+=TPB){ int c=i/4,o=i%4; fnp[c*1024+1020+o]=0.f; }
  __syncthreads();

  // ---- cumsum (block scan over 1000, chunk-of-4 per thread) ----
  {
    int lane=tid&31, wid=tid>>5;
    float l0=0,l1=0,l2=0,l3=0;
    int t0=4*tid;
    if(t0<1000){
      l0=wfp[100+t0];
      l1=l0+wfp[101+t0];
      l2=l1+wfp[102+t0];
      l3=l2+wfp[103+t0];
    }
    float cs=l3;
    float x=cs;
#pragma unroll
    for(int o=1;o<32;o<<=1){ float y=__shfl_up_sync(0xffffffffu,x,o); if(lane>=o) x+=y; }
    if(lane==31) red[wid]=x;
    __syncthreads();
    if(wid==0){
      float z=(lane<8)? red[lane] : 0.f;
#pragma unroll
      for(int o=1;o<8;o<<=1){ float y=__shfl_up_sync(0xffffffffu,z,o); if(lane>=o) z+=y; }
      if(lane<8) red[lane]=z;   // inclusive per-warp totals
    }
    __syncthreads();
    float pre = x - cs + ((wid>0)? red[wid-1] : 0.f);
    if(t0<1000){
      cp[100+t0]=pre+l0; cp[101+t0]=pre+l1; cp[102+t0]=pre+l2; cp[103+t0]=pre+l3;
    }
  }
  __syncthreads();
  // cp reflect halos
  for(int i=tid;i<100;i+=TPB){ cp[i]=cp[200-i]; cp[1100+i]=cp[1098-i]; }

  // ---- d1 = 9-tap derivative (zero-padded) into buf ----
  {
    const float dw0=1.f/280.f, dw1=-4.f/105.f, dw2=0.2f, dw3=-0.8f,
                dw5=0.8f, dw6=-0.2f, dw7=4.f/105.f, dw8=-1.f/280.f;
    for(int t=tid;t<1000;t+=TPB){
      float s=0.f;
      if(t>=4)    s=fmaf(dw0, wfp[ 96+t], s);
      if(t>=3)    s=fmaf(dw1, wfp[ 97+t], s);
      if(t>=2)    s=fmaf(dw2, wfp[ 98+t], s);
      if(t>=1)    s=fmaf(dw3, wfp[ 99+t], s);
      if(t<=998)  s=fmaf(dw5, wfp[101+t], s);
      if(t<=997)  s=fmaf(dw6, wfp[102+t], s);
      if(t<=996)  s=fmaf(dw7, wfp[103+t], s);
      if(t<=995)  s=fmaf(dw8, wfp[104+t], s);
      buf[t]=s;
    }
  }

  // ---- block reductions: wf max, SPE max, sum(w_cum_area) ----
  {
    float vmax=-1e30f, smax=-1e30f, swca=0.f;
    for(int t=tid;t<1000;t+=TPB){ vmax=fmaxf(vmax,wfp[100+t]); smax=fmaxf(smax,g_spe[t]); }
    for(int i=tid;i<124;i+=TPB) swca+=wcaP[i];
    bredMax(vmax,red,&scal[0]);
    bredMax(smax,red,&scal[1]);
    bredSum(swca,red,&scal[2]);
  }
  if(tid==0){
    float h = scal[0]/scal[1];
    float e0=-fmaxf(h-g_wp[0],0.f);
    float e1=-fmaxf(h-g_wp[1],0.f);
    float e2=-fmaxf(h-g_wp[2],0.f);
    float m=fmaxf(e0,fmaxf(e1,e2));
    float p0=expf(e0-m),p1=expf(e1-m),p2=expf(e2-m);
    float is=1.f/(p0+p1+p2);
    scal[3]=p0*is; scal[4]=p1*is; scal[5]=p2*is;
  }
  __syncthreads();

  // ---- cwp[c=3d+r][h] = W[r]*w_comb[d,h,r] (zero-padded to 104) ----
  for(int i=tid;i<1560;i+=TPB){
    int c=i/104, hh=i%104, d=c/3, r=c%3;
    cwp[i] = (hh<101) ? scal[3+r]*g_wcomb[(d*101+hh)*3+r] : 0.f;
  }

  // ---- ds = running mean(51) of d1 (zero-padded) into dsp interior ----
  for(int t=tid;t<1000;t+=TPB){
    float s=0.f;
    int lo = (t-25<0)? 0 : t-25;
    int hi = (t+25>999)? 999 : t+25;
    for(int u=lo;u<=hi;u++) s+=buf[u];
    dsp[100+t]=s*(1.f/51.f);
  }
  __syncthreads();
  for(int i=tid;i<100;i+=TPB){ dsp[i]=dsp[200-i]; dsp[1100+i]=dsp[1098-i]; }
  __syncthreads();

  // ---- fit convs (121/101-tap reflect) -> features1 (relu) into fnp interior ----
  {
    float swcaV = scal[2];
    if(tid<250){
      int t0=4*tid;
      float aca[4]={0,0,0,0}, arl[4]={0,0,0,0}, ax[4]={0,0,0,0}, adv[4]={0,0,0,0};
      conv4r(cp +t0, wcaP, 31, aca);
      conv4r(cp +t0, wrlP, 26, arl);
      conv4r(wfp+t0, wxP , 31, ax );
      conv4r(dsp+t0, wdvP, 31, adv);
#pragma unroll
      for(int j=0;j<4;j++){
        fnp[     10+t0+j] = fmaxf(fmaf(-swcaV,arl[j],aca[j]), 0.f);
        fnp[1024+10+t0+j] = fmaxf(ax[j] , 0.f);
        fnp[2048+10+t0+j] = fmaxf(adv[j], 0.f);
      }
    }
  }
  __syncthreads();

  // ---- channel sums -> normalize -> reflect halos (pad 10) ----
  {
    float s0=0,s1=0,s2=0;
    for(int t=tid;t<1000;t+=TPB){ s0+=fnp[10+t]; s1+=fnp[1034+t]; s2+=fnp[2058+t]; }
    s0=warpRSum(s0); s1=warpRSum(s1); s2=warpRSum(s2);
    int lane=tid&31, wid=tid>>5;
    if(lane==0){ red[wid]=s0; red[8+wid]=s1; red[16+wid]=s2; }
    __syncthreads();
    if(tid==0){
      float S0=0,S1=0,S2=0;
#pragma unroll
      for(int i=0;i<8;i++){ S0+=red[i]; S1+=red[8+i]; S2+=red[16+i]; }
      scal[6]=1.f/(S0+1e-10f); scal[7]=1.f/(S1+1e-10f); scal[8]=1.f/(S2+1e-10f);
    }
    __syncthreads();
  }
  {
    float i0=scal[6], i1=scal[7], i2=scal[8];
    for(int t=tid;t<1000;t+=TPB){ fnp[10+t]*=i0; fnp[1034+t]*=i1; fnp[2058+t]*=i2; }
  }
  __syncthreads();
  for(int i=tid;i<60;i+=TPB){
    int c=i/20, q=i%20;
    float* f=fnp+c*1024;
    if(q<10) f[q]=f[20-q];
    else { int p=1010+(q-10); f[p]=f[2018-p]; }
  }
  __syncthreads();

  // ---- f2 = conv(features1_norm, w_sub) -> f2p interior (+50 halo) ----
  if(tid<250){
    int t0=4*tid;
#pragma unroll 1
    for(int m=0;m<15;m++){
      float acc[4]={0,0,0,0};
      const float* wm = wsubp + m*72;
      conv4<6>(fnp      +t0, wm   , acc);
      conv4<6>(fnp+1024 +t0, wm+24, acc);
      conv4<6>(fnp+2048 +t0, wm+48, acc);
      float* o = f2p + m*1104 + 50 + t0;
      o[0]=acc[0]; o[1]=acc[1]; o[2]=acc[2]; o[3]=acc[3];
    }
  }
  __syncthreads();

  // ---- comb conv (15 x 101-tap, W folded into weights) + softplus ----
  if(tid<250){
    int t0=4*tid;
    float acc[4]={0,0,0,0};
#pragma unroll 1
    for(int c=0;c<15;c++)
      conv4<26>(f2p + c*1104 + t0, cwp + c*104, acc);
#pragma unroll
    for(int j=0;j<4;j++){
      float v=acc[j];
      float sp = (v>0.f) ? v + log1pf(expf(-v)) : log1pf(expf(v));
      buf[t0+j]=sp;
    }
  }
  __syncthreads();

  // ---- amax, masked scale, 1e4-softmax over t ----
  {
    float om=-1e30f;
    for(int t=tid;t<1000;t+=TPB) om=fmaxf(om,buf[t]);
    bredMax(om,red,&scal[9]);
    float amax = scal[9] + 1e-10f;

    float ym=-1e30f;
    for(int t=tid;t<1000;t+=TPB){
      float y = 1e4f * ((buf[t]/amax)*mk[t]);
      buf[t]=y; ym=fmaxf(ym,y);
    }
    bredMax(ym,red,&scal[10]);
    float ymax=scal[10];

    float ssum=0.f;
    for(int t=tid;t<1000;t+=TPB){
      float p=expf(buf[t]-ymax);
      buf[t]=p; ssum+=p;
    }
    bredSum(ssum,red,&scal[11]);
    float isum=1.f/scal[11];
    for(int t=tid;t<1000;t+=TPB) outp[t]=buf[t]*isum;
  }
}

extern "C" void kernel_launch(void* const* d_in, const int* in_sizes, int n_in,
                              void* d_out, int out_size) {
  const float* wf    = (const float*)d_in[0];
  const float* mask  = (const float*)d_in[1];
  const float* SPE   = (const float*)d_in[2];
  const float* wca   = (const float*)d_in[3];
  const float* wx    = (const float*)d_in[4];
  const float* wdv   = (const float*)d_in[5];
  const float* wrl   = (const float*)d_in[6];
  const float* wsub  = (const float*)d_in[7];
  const float* wcomb = (const float*)d_in[8];
  const float* wp    = (const float*)d_in[9];
  float* out = (float*)d_out;

  int B = in_sizes[0] / 1000;
  size_t smem = SMEM_FLOATS * sizeof(float);
  cudaFuncSetAttribute(Spot_48610439856277_kernel,
                       cudaFuncAttributeMaxDynamicSharedMemorySize, (int)smem);
  Spot_48610439856277_kernel<<<B, TPB, smem>>>(wf, mask, SPE, wca, wx, wdv,
                                               wrl, wsub, wcomb, wp, out);
}

// round 6
// speedup vs baseline: 1.9352x; 1.9352x over previous
#include <cuda_runtime.h>
#include <math.h>

#define TPB 256
// ---------------- shared-memory layout (floats) ----------------
// wfp   @0      [1200]  reflect-padded waveform
// cp    @1200   [1200]  reflect-padded cumsum     (later reused as part[520])
// dsp   @2400   [1200]  reflect-padded smoothed deriv
// buf   @3600   [1024]  d1 / prefix / softplus out
// fnp   @4624   [3072]  normalized features + reflect halos (3 x 1024)
// f2b   @7696   [4860]  boundary f2, 15 ch x stride 324 (zero-padded L/R blocks)
// cwp   @12556  [1560]  W-folded comb weights 15 x 104
// wsubp @14116  [1080]  15 x 3 x 24
// wcaE  @15196  [124]   fused cum-area kernel (wca - swca*wrl), padded
// wxP   @15320  [124]
// wdvP  @15444  [124]
// keff  @15568  [372]   composite kernel 3 x 124 (W-weighted)
// red   @15940  [32]
// scal  @15972  [16]
#define SMEM_FLOATS 15988
#define F2B_STRIDE 324

__device__ float g_K3[1116];      // [r][c][124] sample-independent composite
__device__ float g_wcaEff[124];
__device__ float g_speMax;

// ================= precompute kernel (once per launch) =================
__global__ void Spot_pre_kernel(const float* __restrict__ spe,
                                const float* __restrict__ wca,
                                const float* __restrict__ wrl,
                                const float* __restrict__ wsub,
                                const float* __restrict__ wcomb){
  __shared__ float red[32];
  __shared__ float sh[2];
  int tid=threadIdx.x, lane=tid&31, wid=tid>>5;

  float m=-1e30f;
  for(int i=tid;i<1000;i+=TPB) m=fmaxf(m,spe[i]);
#pragma unroll
  for(int o=16;o>0;o>>=1) m=fmaxf(m,__shfl_xor_sync(0xffffffffu,m,o));
  if(lane==0) red[wid]=m;
  __syncthreads();
  if(tid==0){ float mm=red[0]; for(int i=1;i<TPB/32;i++) mm=fmaxf(mm,red[i]);
              sh[0]=mm; g_speMax=mm; }
  __syncthreads();

  float s=0.f;
  for(int i=tid;i<121;i+=TPB) s+=wca[i];
#pragma unroll
  for(int o=16;o>0;o>>=1) s+=__shfl_xor_sync(0xffffffffu,s,o);
  if(lane==0) red[wid]=s;
  __syncthreads();
  if(tid==0){ float ss=0; for(int i=0;i<TPB/32;i++) ss+=red[i]; sh[1]=ss; }
  __syncthreads();
  float swca=sh[1];

  for(int i=tid;i<124;i+=TPB){
    float a =(i<121)? wca[i]:0.f;
    float rl=(i<101)? wrl[i]:0.f;
    g_wcaEff[i]=a - swca*rl;
  }

  // K3[r][c][q] = sum_d sum_k wsub[3d+r][c][k] * wcomb[d][q-k][r]
  for(int e=tid;e<1116;e+=TPB){
    int r=e/372, rem=e-r*372, c=rem/124, q=rem-c*124;
    float acc=0.f;
    if(q<121){
      int klo=(q>100)? (q-100):0;
      int khi=(q<20)? q:20;
      float ad[5]={0,0,0,0,0};
      for(int d=0;d<5;d++){
        const float* ws = wsub + ((3*d+r)*3+c)*21;
        float a2=0.f;
        for(int k=klo;k<=khi;k++)
          a2 = fmaf(ws[k], wcomb[(d*101+(q-k))*3+r], a2);
        ad[d]=a2;
      }
      acc=((ad[0]+ad[1])+(ad[2]+ad[3]))+ad[4];
    }
    g_K3[e]=acc;
  }
}

// ================= helpers =================
__device__ __forceinline__ float warpRMax(float v){
#pragma unroll
  for(int o=16;o>0;o>>=1) v=fmaxf(v,__shfl_xor_sync(0xffffffffu,v,o));
  return v;
}
__device__ __forceinline__ float warpRSum(float v){
#pragma unroll
  for(int o=16;o>0;o>>=1) v+=__shfl_xor_sync(0xffffffffu,v,o);
  return v;
}
__device__ __forceinline__ void bredMax(float v, float* red, float* out){
  int lane=threadIdx.x&31, wid=threadIdx.x>>5;
  v=warpRMax(v);
  if(lane==0) red[wid]=v;
  __syncthreads();
  if(threadIdx.x==0){
    float m=red[0];
#pragma unroll
    for(int i=1;i<TPB/32;i++) m=fmaxf(m,red[i]);
    *out=m;
  }
  __syncthreads();
}
__device__ __forceinline__ void bredSum(float v, float* red, float* out){
  int lane=threadIdx.x&31, wid=threadIdx.x>>5;
  v=warpRSum(v);
  if(lane==0) red[wid]=v;
  __syncthreads();
  if(threadIdx.x==0){
    float s=red[0];
#pragma unroll
    for(int i=1;i<TPB/32;i++) s+=red[i];
    *out=s;
  }
  __syncthreads();
}

// inclusive block scan of 1000 floats (4 per thread); in-place safe.
// caller must __syncthreads() after before reading other threads' results.
__device__ __forceinline__ void scan1000(const float* src, float* dst, float* red){
  int tid=threadIdx.x, lane=tid&31, wid=tid>>5;
  float l0=0,l1=0,l2=0,l3=0;
  int t0=4*tid;
  if(t0<1000){
    l0=src[t0]; l1=l0+src[t0+1]; l2=l1+src[t0+2]; l3=l2+src[t0+3];
  }
  float cs=l3, x=cs;
#pragma unroll
  for(int o=1;o<32;o<<=1){ float y=__shfl_up_sync(0xffffffffu,x,o); if(lane>=o) x+=y; }
  if(lane==31) red[wid]=x;
  __syncthreads();
  if(wid==0){
    float z=(lane<8)? red[lane]:0.f;
#pragma unroll
    for(int o=1;o<8;o<<=1){ float y=__shfl_up_sync(0xffffffffu,z,o); if(lane>=o) z+=y; }
    if(lane<8) red[lane]=z;
  }
  __syncthreads();
  float pre = x - cs + ((wid>0)? red[wid-1]:0.f);
  if(t0<1000){
    dst[t0]=pre+l0; dst[t0+1]=pre+l1; dst[t0+2]=pre+l2; dst[t0+3]=pre+l3;
  }
}

// 4 consecutive outputs, sliding float4 window
#define CONV4_BODY(x0,x1,wv,acc)                                               \
  acc[0]=fmaf(wv.x,x0.x,acc[0]); acc[1]=fmaf(wv.x,x0.y,acc[1]);                \
  acc[2]=fmaf(wv.x,x0.z,acc[2]); acc[3]=fmaf(wv.x,x0.w,acc[3]);                \
  acc[0]=fmaf(wv.y,x0.y,acc[0]); acc[1]=fmaf(wv.y,x0.z,acc[1]);                \
  acc[2]=fmaf(wv.y,x0.w,acc[2]); acc[3]=fmaf(wv.y,x1.x,acc[3]);                \
  acc[0]=fmaf(wv.z,x0.z,acc[0]); acc[1]=fmaf(wv.z,x0.w,acc[1]);                \
  acc[2]=fmaf(wv.z,x1.x,acc[2]); acc[3]=fmaf(wv.z,x1.y,acc[3]);                \
  acc[0]=fmaf(wv.w,x0.w,acc[0]); acc[1]=fmaf(wv.w,x1.x,acc[1]);                \
  acc[2]=fmaf(wv.w,x1.y,acc[2]); acc[3]=fmaf(wv.w,x1.z,acc[3]);

template<int NG>
__device__ __forceinline__ void conv4(const float* __restrict__ src,
                                      const float* __restrict__ w,
                                      float* __restrict__ acc){
  float4 x0 = *reinterpret_cast<const float4*>(src);
#pragma unroll
  for(int g=0; g<NG; g++){
    float4 x1 = *reinterpret_cast<const float4*>(src + 4*g + 4);
    float4 wv = *reinterpret_cast<const float4*>(w + 4*g);
    CONV4_BODY(x0,x1,wv,acc)
    x0=x1;
  }
}
__device__ __forceinline__ void conv4r(const float* __restrict__ src,
                                       const float* __restrict__ w,
                                       int ng, float* __restrict__ acc){
  float4 x0 = *reinterpret_cast<const float4*>(src);
#pragma unroll 2
  for(int g=0; g<ng; g++){
    float4 x1 = *reinterpret_cast<const float4*>(src + 4*g + 4);
    float4 wv = *reinterpret_cast<const float4*>(w + 4*g);
    CONV4_BODY(x0,x1,wv,acc)
    x0=x1;
  }
}

__device__ __forceinline__ float softplusf(float v){
  return (v>0.f) ? v + log1pf(expf(-v)) : log1pf(expf(v));
}

// ================= main kernel =================
__global__ void __launch_bounds__(TPB,3) Spot_48610439856277_kernel(
  const float* __restrict__ g_wf, const float* __restrict__ g_mask,
  const float* __restrict__ g_wx, const float* __restrict__ g_wdv,
  const float* __restrict__ g_wsub, const float* __restrict__ g_wcomb,
  const float* __restrict__ g_wp,
  float* __restrict__ g_out)
{
  extern __shared__ float sm[];
  float* wfp  = sm;
  float* cp   = sm + 1200;
  float* dsp  = sm + 2400;
  float* buf  = sm + 3600;
  float* fnp  = sm + 4624;
  float* f2b  = sm + 7696;
  float* cwp  = sm + 12556;
  float* wsubp= sm + 14116;
  float* wcaE = sm + 15196;
  float* wxP  = sm + 15320;
  float* wdvP = sm + 15444;
  float* keff = sm + 15568;
  float* red  = sm + 15940;
  float* scal = sm + 15972;
  float* part = cp; // reuse after fit convs

  const int tid = threadIdx.x;
  const int b   = blockIdx.x;
  const float* wf = g_wf  + (size_t)b*1000;
  const float* mk = g_mask+ (size_t)b*1000;
  float* outp     = g_out + (size_t)b*1000;

  // ---- loads + pads ----
  for(int i=tid;i<1200;i+=TPB){
    int j=i-100; j = (j<0) ? -j : (j>999 ? 1998-j : j);
    wfp[i]=wf[j];
  }
  for(int i=tid;i<124;i+=TPB){
    wcaE[i]=g_wcaEff[i];
    wxP[i] =(i<121)? g_wx[i] :0.f;
    wdvP[i]=(i<121)? g_wdv[i]:0.f;
  }
  for(int i=tid;i<1080;i+=TPB){
    int m=i/72, rem=i%72, cin=rem/24, k=rem%24;
    wsubp[i] = (k<21)? g_wsub[(m*3+cin)*21+k] : 0.f;
  }
  // f2b zero pads: per channel [0,50), [150,160), [260,324)  -> 124 each
  for(int i=tid;i<15*124;i+=TPB){
    int c=i/124, j=i%124;
    int off = (j<50)? j : (j<60? 150+(j-50) : 260+(j-60));
    f2b[c*F2B_STRIDE+off]=0.f;
  }
  for(int i=tid;i<12;i+=TPB){ fnp[(i/4)*1024+1020+(i%4)]=0.f; }
  __syncthreads();

  // ---- cumsum wfp -> cp interior ----
  scan1000(wfp+100, cp+100, red);

  // ---- d1 (9-tap zero-padded derivative) -> buf ----
  {
    const float dw0=1.f/280.f, dw1=-4.f/105.f, dw2=0.2f, dw3=-0.8f,
                dw5=0.8f, dw6=-0.2f, dw7=4.f/105.f, dw8=-1.f/280.f;
    for(int t=tid;t<1000;t+=TPB){
      float s=0.f;
      if(t>=4)    s=fmaf(dw0, wfp[ 96+t], s);
      if(t>=3)    s=fmaf(dw1, wfp[ 97+t], s);
      if(t>=2)    s=fmaf(dw2, wfp[ 98+t], s);
      if(t>=1)    s=fmaf(dw3, wfp[ 99+t], s);
      if(t<=998)  s=fmaf(dw5, wfp[101+t], s);
      if(t<=997)  s=fmaf(dw6, wfp[102+t], s);
      if(t<=996)  s=fmaf(dw7, wfp[103+t], s);
      if(t<=995)  s=fmaf(dw8, wfp[104+t], s);
      buf[t]=s;
    }
  }
  __syncthreads();
  for(int i=tid;i<100;i+=TPB){ cp[i]=cp[200-i]; cp[1100+i]=cp[1098-i]; }

  // ---- wf max -> gate W ----
  {
    float vmax=-1e30f;
    for(int t=tid;t<1000;t+=TPB) vmax=fmaxf(vmax,wfp[100+t]);
    bredMax(vmax,red,&scal[0]);
  }
  if(tid==0){
    float h = scal[0]/g_speMax;
    float e0=-fmaxf(h-g_wp[0],0.f);
    float e1=-fmaxf(h-g_wp[1],0.f);
    float e2=-fmaxf(h-g_wp[2],0.f);
    float m=fmaxf(e0,fmaxf(e1,e2));
    float p0=expf(e0-m),p1=expf(e1-m),p2=expf(e2-m);
    float is=1.f/(p0+p1+p2);
    scal[3]=p0*is; scal[4]=p1*is; scal[5]=p2*is;
  }
  __syncthreads();

  // ---- running mean(51) via prefix scan of d1 ----
  scan1000(buf, buf, red);
  __syncthreads();
  for(int t=tid;t<1000;t+=TPB){
    int hi = (t+25>999)? 999 : t+25;
    float p = buf[hi] - ((t>=26)? buf[t-26] : 0.f);
    dsp[100+t]=p*(1.f/51.f);
  }
  __syncthreads();
  for(int i=tid;i<100;i+=TPB){ dsp[i]=dsp[200-i]; dsp[1100+i]=dsp[1098-i]; }

  // ---- per-sample weights: cwp (boundary comb) + keff (composite) ----
  for(int i=tid;i<1560;i+=TPB){
    int c=i/104, hh=i%104, d=c/3, r=c%3;
    cwp[i] = (hh<101) ? scal[3+r]*g_wcomb[(d*101+hh)*3+r] : 0.f;
  }
  for(int i=tid;i<372;i+=TPB){
    keff[i] = scal[3]*g_K3[i] + scal[4]*g_K3[372+i] + scal[5]*g_K3[744+i];
  }
  __syncthreads();

  // ---- fit convs (121-tap reflect) -> features1 (relu) ----
  if(tid<250){
    int t0=4*tid;
    {
      float a[4]={0,0,0,0};
      conv4r(cp +t0, wcaE, 31, a);
#pragma unroll
      for(int j=0;j<4;j++) fnp[10+t0+j]=fmaxf(a[j],0.f);
    }
    {
      float a[4]={0,0,0,0};
      conv4r(wfp+t0, wxP , 31, a);
#pragma unroll
      for(int j=0;j<4;j++) fnp[1034+t0+j]=fmaxf(a[j],0.f);
    }
    {
      float a[4]={0,0,0,0};
      conv4r(dsp+t0, wdvP, 31, a);
#pragma unroll
      for(int j=0;j<4;j++) fnp[2058+t0+j]=fmaxf(a[j],0.f);
    }
  }
  __syncthreads();

  // ---- channel sums -> normalize -> reflect halos (pad 10) ----
  {
    float s0=0,s1=0,s2=0;
    for(int t=tid;t<1000;t+=TPB){ s0+=fnp[10+t]; s1+=fnp[1034+t]; s2+=fnp[2058+t]; }
    s0=warpRSum(s0); s1=warpRSum(s1); s2=warpRSum(s2);
    int lane=tid&31, wid=tid>>5;
    if(lane==0){ red[wid]=s0; red[8+wid]=s1; red[16+wid]=s2; }
    __syncthreads();
    if(tid==0){
      float S0=0,S1=0,S2=0;
#pragma unroll
      for(int i=0;i<8;i++){ S0+=red[i]; S1+=red[8+i]; S2+=red[16+i]; }
      scal[6]=1.f/(S0+1e-10f); scal[7]=1.f/(S1+1e-10f); scal[8]=1.f/(S2+1e-10f);
    }
    __syncthreads();
  }
  {
    float i0=scal[6], i1=scal[7], i2=scal[8];
    for(int t=tid;t<1000;t+=TPB){ fnp[10+t]*=i0; fnp[1034+t]*=i1; fnp[2058+t]*=i2; }
  }
  __syncthreads();
  for(int i=tid;i<60;i+=TPB){
    int c=i/20, q=i%20;
    float* f=fnp+c*1024;
    if(q<10) f[q]=f[20-q];
    else { int p=1010+(q-10); f[p]=f[2018-p]; }
  }
  __syncthreads();

  // ---- boundary f2: 15 ch x ([0,100) and [900,1000)) -> f2b ----
#pragma unroll 1
  for(int rr=0; rr<3; rr++){
    if(tid<250){
      int u=rr*250+tid;
      int m=u/50, g=u%50;
      int u0 = (g<25)? 4*g : (900+4*(g-25));
      int so = (g<25)? (50+4*g) : (160+4*(g-25));
      float acc[4]={0,0,0,0};
      const float* wm = wsubp + m*72;
      conv4<6>(fnp      + u0, wm   , acc);
      conv4<6>(fnp+1024 + u0, wm+24, acc);
      conv4<6>(fnp+2048 + u0, wm+48, acc);
      float* o = f2b + m*F2B_STRIDE + so;
      o[0]=acc[0]; o[1]=acc[1]; o[2]=acc[2]; o[3]=acc[3];
    }
  }
  __syncthreads();

  // ---- interior composite conv (t in [50,950)) + softplus ----
  if(tid<225){
    int t0=50+4*tid;
    float acc[4]={0,0,0,0};
    conv4r(fnp      + 4*tid, keff    , 31, acc);
    conv4r(fnp+1024 + 4*tid, keff+124, 31, acc);
    conv4r(fnp+2048 + 4*tid, keff+248, 31, acc);
#pragma unroll
    for(int j=0;j<4;j++) buf[t0+j]=softplusf(acc[j]);
  }
  // ---- boundary comb partials (channel-split over 130 threads) ----
  if(tid<130){
    int g26=tid/5, p=tid%5;
    int side=g26/13, G=g26%13;
    const float* srcb = f2b + side*160 + 4*G;
    float acc[4]={0,0,0,0};
    conv4r(srcb + (3*p  )*F2B_STRIDE, cwp+(3*p  )*104, 26, acc);
    conv4r(srcb + (3*p+1)*F2B_STRIDE, cwp+(3*p+1)*104, 26, acc);
    conv4r(srcb + (3*p+2)*F2B_STRIDE, cwp+(3*p+2)*104, 26, acc);
    float* pp = part + (g26*5+p)*4;
    pp[0]=acc[0]; pp[1]=acc[1]; pp[2]=acc[2]; pp[3]=acc[3];
  }
  __syncthreads();
  if(tid<104){
    int g26=tid/4, j=tid%4;
    int side=g26/13, G=g26%13;
    int t = side ? (950+4*G+j) : (4*G+j);
    bool valid = side ? (t<1000) : (t<50);
    if(valid){
      float v=0.f;
#pragma unroll
      for(int p=0;p<5;p++) v+=part[(g26*5+p)*4+j];
      buf[t]=softplusf(v);
    }
  }
  __syncthreads();

  // ---- amax, masked scale, 1e4-softmax over t ----
  {
    float om=-1e30f;
    for(int t=tid;t<1000;t+=TPB) om=fmaxf(om,buf[t]);
    bredMax(om,red,&scal[9]);
    float amax = scal[9] + 1e-10f;

    float ym=-1e30f;
    for(int t=tid;t<1000;t+=TPB){
      float y = 1e4f * ((buf[t]/amax)*mk[t]);
      buf[t]=y; ym=fmaxf(ym,y);
    }
    bredMax(ym,red,&scal[10]);
    float ymax=scal[10];

    float ssum=0.f;
    for(int t=tid;t<1000;t+=TPB){
      float p=expf(buf[t]-ymax);
      buf[t]=p; ssum+=p;
    }
    bredSum(ssum,red,&scal[11]);
    float isum=1.f/scal[11];
    for(int t=tid;t<1000;t+=TPB) outp[t]=buf[t]*isum;
  }
}

extern "C" void kernel_launch(void* const* d_in, const int* in_sizes, int n_in,
                              void* d_out, int out_size) {
  const float* wf    = (const float*)d_in[0];
  const float* mask  = (const float*)d_in[1];
  const float* SPE   = (const float*)d_in[2];
  const float* wca   = (const float*)d_in[3];
  const float* wx    = (const float*)d_in[4];
  const float* wdv   = (const float*)d_in[5];
  const float* wrl   = (const float*)d_in[6];
  const float* wsub  = (const float*)d_in[7];
  const float* wcomb = (const float*)d_in[8];
  const float* wp    = (const float*)d_in[9];
  float* out = (float*)d_out;

  int B = in_sizes[0] / 1000;
  size_t smem = SMEM_FLOATS * sizeof(float);
  cudaFuncSetAttribute(Spot_48610439856277_kernel,
                       cudaFuncAttributeMaxDynamicSharedMemorySize, (int)smem);

  Spot_pre_kernel<<<1, TPB>>>(SPE, wca, wrl, wsub, wcomb);
  Spot_48610439856277_kernel<<<B, TPB, smem>>>(wf, mask, wx, wdv,
                                               wsub, wcomb, wp, out);
}